// round 17
// baseline (speedup 1.0000x reference)
#include <cuda_runtime.h>
#include <cstdint>
#include <math.h>

#define FULL_MASK 0xffffffffu
typedef unsigned long long ull;

// ---- f32x2 packed-math helpers ----
__device__ __forceinline__ ull pk2(float lo, float hi) {
    ull r; asm("mov.b64 %0,{%1,%2};" : "=l"(r) : "f"(lo), "f"(hi)); return r;
}
__device__ __forceinline__ void up2(ull v, float& lo, float& hi) {
    asm("mov.b64 {%0,%1},%2;" : "=f"(lo), "=f"(hi) : "l"(v));
}
__device__ __forceinline__ ull fma2(ull a, ull b, ull c) {
    ull d; asm("fma.rn.f32x2 %0,%1,%2,%3;" : "=l"(d) : "l"(a), "l"(b), "l"(c)); return d;
}
__device__ __forceinline__ ull mul2(ull a, ull b) {
    ull d; asm("mul.rn.f32x2 %0,%1,%2;" : "=l"(d) : "l"(a), "l"(b)); return d;
}
__device__ __forceinline__ ull add2(ull a, ull b) {
    ull d; asm("add.rn.f32x2 %0,%1,%2;" : "=l"(d) : "l"(a), "l"(b)); return d;
}
__device__ __forceinline__ float tanh_hw(float x) {
    float y; asm("tanh.approx.f32 %0, %1;" : "=f"(y) : "f"(x)); return y;
}
__device__ __forceinline__ uint32_t smem_u32(const void* p) {
    uint32_t a;
    asm("{ .reg .u64 t; cvta.to.shared.u64 t, %1; cvt.u32.u64 %0, t; }"
        : "=r"(a) : "l"(p));
    return a;
}
__device__ __forceinline__ float ld_cluster_f32(uint32_t my_addr, uint32_t rank) {
    uint32_t ra; float v;
    asm volatile("mapa.shared::cluster.u32 %0, %1, %2;" : "=r"(ra) : "r"(my_addr), "r"(rank));
    asm volatile("ld.shared::cluster.f32 %0, [%1];" : "=f"(v) : "r"(ra));
    return v;
}
#define CLUSTER_SYNC() do { \
    asm volatile("barrier.cluster.arrive.aligned;" ::: "memory"); \
    asm volatile("barrier.cluster.wait.aligned;"   ::: "memory"); } while (0)

#define THREADS 256
#define TPT     4          // timesteps per thread (two packed pair-streams)
#define KCTA    (THREADS * TPT)   // 1024
#define CSZ     4
#define KSUPER  (KCTA * CSZ)
#define NSWEEP  3          // calibrated: 2 sweeps -> 6.3e-3 rel (fails); 3 -> 3.4e-5
#define NWARP   (THREADS / 32)    // 8

// Parallel-in-time Picard, cluster edition, 4 timesteps/thread, sweep-0
// shortcut, and 2-way split pre-activation accumulators (halves the serial
// fma2 chain feeding each tanh: ~68 -> ~36 cyc per hidden unit).
__global__ __launch_bounds__(THREADS, 1) __cluster_dims__(CSZ, 1, 1)
void ode_picard_kernel(const float* __restrict__ x,
                       const float* __restrict__ W1,
                       const float* __restrict__ b1,
                       const float* __restrict__ b2,
                       const float* __restrict__ W2,
                       float* __restrict__ out,
                       int T) {
    extern __shared__ char smx[];
    ull*        w1dup = (ull*)smx;                       // [64][16] (w,w)
    ull*        w2dup = w1dup + 64 * 16;                 // [64][16] (w,w)/sr
    ulonglong2* xbv   = (ulonglong2*)(w2dup + 64 * 16);  // [64] {(w1x,w1x),(b1,b1)}
    ull*        upk   = (ull*)(xbv + 64);                // [64] (U_j, U_j) sweep-0
    ull*        b2dup = upk + 64;                        // [16] (b2/sr, b2/sr)
    float*      A     = (float*)(b2dup + 16);            // [16][KCTA] ys_est
    float*      WT    = A + 16 * KCTA;                   // [8 warps][16]
    float*      carry = WT + NWARP * 16;                 // [16]
    float*      rtot  = carry + 16;                      // [16]
    float*      rbase = rtot + 16;                       // [16]
    float*      cnew  = rbase + 16;                      // [16]

    const int b = blockIdx.x / CSZ;
    uint32_t rank;
    asm("mov.u32 %0, %%cluster_ctarank;" : "=r"(rank));
    const int tid  = threadIdx.x;
    const int lane = tid & 31;
    const int wid  = tid >> 5;
    const float inv_sr = 1.0f / 44100.0f;
    const int nsteps = T - 1;

    // ---- prologue: duplicated-packed weights into smem ----
    if (tid < 64) {
        const int j = tid;
        ulonglong2 xb;
        xb.x = pk2(W1[j], W1[j]);
        xb.y = pk2(b1[j], b1[j]);
        xbv[j] = xb;
        for (int k = 0; k < 16; ++k) {
            const float w1v = W1[(k + 1) * 64 + j];
            w1dup[j * 16 + k] = pk2(w1v, w1v);
            const float w2v = W2[j * 16 + k] * inv_sr;
            w2dup[j * 16 + k] = pk2(w2v, w2v);
        }
    }
    if (tid < 16) {
        const float bv = b2[tid] * inv_sr;
        b2dup[tid] = pk2(bv, bv);
        carry[tid] = 0.0f;
    }
    __syncthreads();

    const uint32_t rtot_addr = smem_u32(rtot + (tid & 15));
    const int nsuper = (nsteps + KSUPER - 1) / KSUPER;
    const int tl = TPT * tid;                // first local step of this thread

    for (int blk = 0; blk < nsuper; ++blk) {
        const int s0 = blk * KSUPER + (int)rank * KCTA + tl;
        const bool v1 = s0 < nsteps,     v2 = s0 + 1 < nsteps;
        const bool v3 = s0 + 2 < nsteps, v4 = s0 + 3 < nsteps;
        const float x1 = v1 ? x[(s0)     * 32 + b] : 0.0f;
        const float x2 = v2 ? x[(s0 + 1) * 32 + b] : 0.0f;
        const float x3 = v3 ? x[(s0 + 2) * 32 + b] : 0.0f;
        const float x4 = v4 ? x[(s0 + 3) * 32 + b] : 0.0f;
        const ull xpA = pk2(x1, x2);
        const ull xpB = pk2(x3, x4);

        // ---- sweep-0 shortcut: U_j = b1_j + W1s^T carry (once/superblock) ----
        if (tid < 64) {
            const int j = tid;
            float u = b1[j];
            const float* w1c = W1 + 64 + j;       // rows 1..16, column j
#pragma unroll
            for (int k = 0; k < 16; ++k)
                u = fmaf(carry[k], w1c[k * 64], u);
            upk[j] = pk2(u, u);
        }

        for (int sw = 0; sw < NSWEEP; ++sw) {
            __syncthreads();   // upk/A/carry/WT visibility

            ull accA[16], accB[16];
#pragma unroll
            for (int m = 0; m < 16; ++m) { accA[m] = b2dup[m]; accB[m] = b2dup[m]; }

            if (sw == 0) {
                // ---- sweep 0: a = U_j + x*w0 (W1 contraction pre-folded) ----
#pragma unroll 4
                for (int j = 0; j < 64; ++j) {
                    const ull w0 = xbv[j].x;
                    const ull u  = upk[j];
                    const ull apA = fma2(xpA, w0, u);
                    const ull apB = fma2(xpB, w0, u);
                    float a1, a2, a3, a4;
                    up2(apA, a1, a2);
                    up2(apB, a3, a4);
                    const ull hpA = pk2(tanh_hw(a1), tanh_hw(a2));
                    const ull hpB = pk2(tanh_hw(a3), tanh_hw(a4));
                    const ulonglong2* w2r =
                        reinterpret_cast<const ulonglong2*>(w2dup + j * 16);
#pragma unroll
                    for (int kk = 0; kk < 8; ++kk) {
                        const ulonglong2 w = w2r[kk];
                        accA[2 * kk]     = fma2(hpA, w.x, accA[2 * kk]);
                        accB[2 * kk]     = fma2(hpB, w.x, accB[2 * kk]);
                        accA[2 * kk + 1] = fma2(hpA, w.y, accA[2 * kk + 1]);
                        accB[2 * kk + 1] = fma2(hpB, w.y, accB[2 * kk + 1]);
                    }
                }
            } else {
                // ---- sweeps 1+: full MLP, split pre-activation chains ----
                ull yspA[16], yspB[16];
#pragma unroll
                for (int k = 0; k < 16; ++k) {
                    const float4 f = *reinterpret_cast<const float4*>(A + k * KCTA + tl);
                    yspA[k] = pk2(f.x, f.y);
                    yspB[k] = pk2(f.z, f.w);
                }
#pragma unroll 2
                for (int j = 0; j < 64; ++j) {
                    const ulonglong2 xb = xbv[j];
                    const ulonglong2* w1r =
                        reinterpret_cast<const ulonglong2*>(w1dup + j * 16);
                    // two half-chains per stream (kk 0-3 and 4-7)
                    ull apA0 = fma2(xpA, xb.x, xb.y);
                    ull apB0 = fma2(xpB, xb.x, xb.y);
                    const ulonglong2 w4 = w1r[4];
                    ull apA1 = mul2(yspA[8], w4.x);
                    ull apB1 = mul2(yspB[8], w4.x);
                    apA1 = fma2(yspA[9], w4.y, apA1);
                    apB1 = fma2(yspB[9], w4.y, apB1);
#pragma unroll
                    for (int kk = 0; kk < 4; ++kk) {
                        const ulonglong2 w = w1r[kk];      // broadcast LDS.128
                        apA0 = fma2(yspA[2 * kk],     w.x, apA0);
                        apB0 = fma2(yspB[2 * kk],     w.x, apB0);
                        apA0 = fma2(yspA[2 * kk + 1], w.y, apA0);
                        apB0 = fma2(yspB[2 * kk + 1], w.y, apB0);
                    }
#pragma unroll
                    for (int kk = 5; kk < 8; ++kk) {
                        const ulonglong2 w = w1r[kk];
                        apA1 = fma2(yspA[2 * kk],     w.x, apA1);
                        apB1 = fma2(yspB[2 * kk],     w.x, apB1);
                        apA1 = fma2(yspA[2 * kk + 1], w.y, apA1);
                        apB1 = fma2(yspB[2 * kk + 1], w.y, apB1);
                    }
                    const ull apA = add2(apA0, apA1);
                    const ull apB = add2(apB0, apB1);
                    float a1, a2, a3, a4;
                    up2(apA, a1, a2);
                    up2(apB, a3, a4);
                    const ull hpA = pk2(tanh_hw(a1), tanh_hw(a2));
                    const ull hpB = pk2(tanh_hw(a3), tanh_hw(a4));
                    const ulonglong2* w2r =
                        reinterpret_cast<const ulonglong2*>(w2dup + j * 16);
#pragma unroll
                    for (int kk = 0; kk < 8; ++kk) {
                        const ulonglong2 w = w2r[kk];      // broadcast LDS.128
                        accA[2 * kk]     = fma2(hpA, w.x, accA[2 * kk]);
                        accB[2 * kk]     = fma2(hpB, w.x, accB[2 * kk]);
                        accA[2 * kk + 1] = fma2(hpA, w.y, accA[2 * kk + 1]);
                        accB[2 * kk + 1] = fma2(hpB, w.y, accB[2 * kk + 1]);
                    }
                }
            }

            // ---- unpack, mask tail, build per-thread cumulative sums ----
            float c1[16], c2[16], c3[16], inc[16], sig[16];
#pragma unroll
            for (int m = 0; m < 16; ++m) {
                float d1, d2, d3, d4;
                up2(accA[m], d1, d2);
                up2(accB[m], d3, d4);
                if (!v1) d1 = 0.0f;
                if (!v2) d2 = 0.0f;
                if (!v3) d3 = 0.0f;
                if (!v4) d4 = 0.0f;
                c1[m]  = d1;
                c2[m]  = d1 + d2;
                c3[m]  = c2[m] + d3;
                sig[m] = c3[m] + d4;
                inc[m] = sig[m];
            }

            // ---- warp inclusive scan of per-thread sums (16 dims) ----
#pragma unroll
            for (int off = 1; off < 32; off <<= 1) {
#pragma unroll
                for (int m = 0; m < 16; ++m) {
                    const float tv = __shfl_up_sync(FULL_MASK, inc[m], off);
                    if (lane >= off) inc[m] += tv;
                }
            }
            if (lane == 31) {
#pragma unroll
                for (int m = 0; m < 16; ++m) WT[wid * 16 + m] = inc[m];
            }
            __syncthreads();

            // ---- this rank's block total -> rtot ----
            if (tid < 16) {
                float s = 0.0f;
                for (int w = 0; w < NWARP; ++w) s += WT[w * 16 + tid];
                rtot[tid] = s;
            }
            CLUSTER_SYNC();

            // ---- cross-rank offsets + next carry ----
            if (tid < 16) {
                float base = carry[tid];
                float all  = 0.0f;
                for (int r = 0; r < CSZ; ++r) {
                    const float v = ld_cluster_f32(rtot_addr, (uint32_t)r);
                    all += v;
                    if (r < (int)rank) base += v;
                }
                rbase[tid] = base;
                cnew[tid]  = carry[tid] + all;
            }
            CLUSTER_SYNC();

            // ---- cross-warp offsets within my CTA ----
            float wofs = 0.0f;
            if (lane < 16) {
                wofs = rbase[lane];
                for (int w = 0; w < wid; ++w) wofs += WT[w * 16 + lane];
            }

            // ---- exclusive states before my four steps ----
            if (sw < NSWEEP - 1) {
#pragma unroll
                for (int m = 0; m < 16; ++m) {
                    const float wo = __shfl_sync(FULL_MASK, wofs, m);
                    const float ex = wo + (inc[m] - sig[m]);
                    float4 f;
                    f.x = ex;
                    f.y = ex + c1[m];
                    f.z = ex + c2[m];
                    f.w = ex + c3[m];
                    *reinterpret_cast<float4*>(A + m * KCTA + tl) = f;
                }
            } else {
                // final sweep: emit trajectory + advance carry replica
                {
                    const float wo = __shfl_sync(FULL_MASK, wofs, 0);
                    const float ex = wo + (inc[0] - sig[0]);
                    if (v1) out[(s0)     * 32 + b] = ex;
                    if (v2) out[(s0 + 1) * 32 + b] = ex + c1[0];
                    if (v3) out[(s0 + 2) * 32 + b] = ex + c2[0];
                    if (v4) out[(s0 + 3) * 32 + b] = ex + c3[0];
                }
                if (tid < 16) carry[tid] = cnew[tid];
                __syncthreads();   // carry final before next superblock's upk
            }
        }
    }

    __syncthreads();
    if (rank == 0 && tid == 0) out[nsteps * 32 + b] = carry[0];  // y_full[T-1]
}

extern "C" void kernel_launch(void* const* d_in, const int* in_sizes, int n_in,
                              void* d_out, int out_size) {
    const float* x  = (const float*)d_in[0];
    const float* W1 = (const float*)d_in[1];
    const float* b1 = (const float*)d_in[2];
    const float* W2 = (const float*)d_in[3];
    const float* b2 = (const float*)d_in[4];
    float* out = (float*)d_out;

    const int T = in_sizes[0] / 32;   // x is (T, B=32, F=1)

    const size_t smem_bytes =
        (64 * 16 + 64 * 16 + 64 + 16) * sizeof(ull) +      // w1dup, w2dup, upk, b2dup
        64 * sizeof(ulonglong2) +                          // xbv
        (16 * KCTA + NWARP * 16 + 16 * 4) * sizeof(float) + 256;
    cudaFuncSetAttribute(ode_picard_kernel,
                         cudaFuncAttributeMaxDynamicSharedMemorySize,
                         (int)smem_bytes);
    ode_picard_kernel<<<32 * CSZ, THREADS, smem_bytes>>>(x, W1, b1, b2, W2, out, T);
}